// round 17
// baseline (speedup 1.0000x reference)
#include <cuda_runtime.h>
#include <cuda_bf16.h>

#define Bb 16
#define Cc 128
#define Hh 128
#define Ww 128
#define Nn 16384          // Hh*Ww
#define SPLITG 16         // split-K for Gram
#define KCHUNK_G 1024     // Nn / SPLITG

// ---------------- scratch (static device globals, 16B-aligned) ----------------
static __device__ __align__(16) float g_part[SPLITG][Bb][Cc][Cc];  // P partials
static __device__ __align__(16) __nv_bfloat16 g_Gh[Bb][Cc][Cc];    // G hi
static __device__ __align__(16) __nv_bfloat16 g_Gl[Bb][Cc][Cc];    // G lo
static __device__ __align__(16) float g_m[Bb][Cc];                 // row max of G
static __device__ __align__(16) float g_S[Bb][Nn];                 // column sums (exact)
static __device__ __align__(16) float g_att2[(size_t)Bb * Cc * Nn];// pre-conv tensor

// ---------------- mma / ldmatrix helpers (plain PTX, sm_80+) ----------------
__device__ __forceinline__ unsigned smem_u32(const void* p) {
    unsigned a;
    asm("{ .reg .u64 t; cvta.to.shared.u64 t, %1; cvt.u32.u64 %0, t; }"
        : "=r"(a) : "l"(p));
    return a;
}
__device__ __forceinline__ void ldsm4(unsigned* r, unsigned addr) {
    asm volatile("ldmatrix.sync.aligned.m8n8.x4.shared.b16 {%0,%1,%2,%3}, [%4];"
                 : "=r"(r[0]), "=r"(r[1]), "=r"(r[2]), "=r"(r[3]) : "r"(addr));
}
__device__ __forceinline__ void ldsm4t(unsigned* r, unsigned addr) {
    asm volatile("ldmatrix.sync.aligned.m8n8.x4.trans.shared.b16 {%0,%1,%2,%3}, [%4];"
                 : "=r"(r[0]), "=r"(r[1]), "=r"(r[2]), "=r"(r[3]) : "r"(addr));
}
__device__ __forceinline__ void mma16816(float* c, const unsigned* a, const unsigned* b) {
    asm volatile(
        "mma.sync.aligned.m16n8k16.row.col.f32.bf16.bf16.f32 "
        "{%0,%1,%2,%3}, {%4,%5,%6,%7}, {%8,%9}, {%0,%1,%2,%3};"
        : "+f"(c[0]), "+f"(c[1]), "+f"(c[2]), "+f"(c[3])
        : "r"(a[0]), "r"(a[1]), "r"(a[2]), "r"(a[3]), "r"(b[0]), "r"(b[1]));
}
// scale packed bf16x2 by 0.5 (exact: exponent decrement)
__device__ __forceinline__ unsigned bhalf(unsigned v) {
    __nv_bfloat162 h = *(__nv_bfloat162*)&v;
    __nv_bfloat162 c = __floats2bfloat162_rn(0.5f, 0.5f);
    __nv_bfloat162 r = __hmul2(h, c);
    return *(unsigned*)&r;
}

// split 8 fp32 -> 8 bf16 hi + 8 bf16 lo (packed as uint4 each)
__device__ __forceinline__ void split8(const float4 v0, const float4 v1,
                                       uint4& h, uint4& l) {
    __nv_bfloat162 h0 = __floats2bfloat162_rn(v0.x, v0.y);
    __nv_bfloat162 h1 = __floats2bfloat162_rn(v0.z, v0.w);
    __nv_bfloat162 h2 = __floats2bfloat162_rn(v1.x, v1.y);
    __nv_bfloat162 h3 = __floats2bfloat162_rn(v1.z, v1.w);
    unsigned b0 = *(unsigned*)&h0, b1 = *(unsigned*)&h1;
    unsigned b2 = *(unsigned*)&h2, b3 = *(unsigned*)&h3;
    float f0x = __uint_as_float(b0 << 16), f0y = __uint_as_float(b0 & 0xffff0000u);
    float f1x = __uint_as_float(b1 << 16), f1y = __uint_as_float(b1 & 0xffff0000u);
    float f2x = __uint_as_float(b2 << 16), f2y = __uint_as_float(b2 & 0xffff0000u);
    float f3x = __uint_as_float(b3 << 16), f3y = __uint_as_float(b3 & 0xffff0000u);
    __nv_bfloat162 l0 = __floats2bfloat162_rn(v0.x - f0x, v0.y - f0y);
    __nv_bfloat162 l1 = __floats2bfloat162_rn(v0.z - f1x, v0.w - f1y);
    __nv_bfloat162 l2 = __floats2bfloat162_rn(v1.x - f2x, v1.y - f2y);
    __nv_bfloat162 l3 = __floats2bfloat162_rn(v1.z - f3x, v1.w - f3y);
    h = make_uint4(b0, b1, b2, b3);
    l = make_uint4(*(unsigned*)&l0, *(unsigned*)&l1,
                   *(unsigned*)&l2, *(unsigned*)&l3);
}

// swizzled byte offset, 128B rows (gram tiles): row 0..127, col16 0..7
__device__ __forceinline__ unsigned sw128(int row, int col16) {
    return (unsigned)(row * 128 + ((col16 ^ (row & 7)) << 4));
}
// swizzled byte offset, 256B rows (gemm2 resident A): row 0..127, col16 0..15
__device__ __forceinline__ unsigned sw256(int row, int col16) {
    return (unsigned)(row * 256 + ((((col16 ^ row) & 7) | (col16 & 8)) << 4));
}

// ---------------------------------------------------------------------------
// Kernel 1: Gram split-K via HMMA, SYMMETRIC 2-pass:
//   P = 0.5*H*H^T + H*L^T   (G recovered later as P + P^T)
// + fused exact fp32 column sums S.
// grid (SPLITG, Bb) = one full wave at 2 CTA/SM.
// dyn smem: [0,65536) tile double-buffer {H,L}; [65536,+16896) sS[2][64][33].
// ---------------------------------------------------------------------------
__global__ __launch_bounds__(256, 2)
void k_gram_mma(const float* __restrict__ x) {
    extern __shared__ __align__(16) char dsm[];
    float* sS = (float*)(dsm + 65536);

    const int b  = blockIdx.y;
    const int sp = blockIdx.x;
    const int tid = threadIdx.x;
    const int wid = tid >> 5, lane = tid & 31;
    const int wm = wid & 3, wn = wid >> 2;
    const unsigned uBase = smem_u32(dsm);

    float acc[2][8][4];
#pragma unroll
    for (int mi = 0; mi < 2; mi++)
#pragma unroll
        for (int nb = 0; nb < 8; nb++)
#pragma unroll
            for (int q = 0; q < 4; q++) acc[mi][nb][q] = 0.f;

    const int arow = wm * 32 + (lane & 15);
    const int asel = lane >> 4;
    const int brow = (lane & 7) + ((lane >> 4) & 1) * 8;
    const int bsel = (lane >> 3) & 1;

    const size_t kb0 = (size_t)sp * KCHUNK_G;
    const int NIT = KCHUNK_G / 64;   // 16

    const int prow = tid >> 3, pc8 = tid & 7;         // staging: row, col16
    float4 pv[8];

    // prologue: chunk 0
#pragma unroll
    for (int q = 0; q < 4; q++) {
        const float* src = x + (size_t)(b * Cc + prow + q * 32) * Nn + kb0 + pc8 * 8;
        pv[2 * q]     = *(const float4*)src;
        pv[2 * q + 1] = *(const float4*)(src + 4);
    }

    for (int it = 0; it < NIT; it++) {
        const unsigned bufo = (unsigned)(it & 1) * 32768u;
        float* sSb = sS + (it & 1) * (64 * 33);
        // exact fp32 column partial sums over this thread's 4 row-groups
        {
            float cs0 = pv[0].x + pv[2].x + pv[4].x + pv[6].x;
            float cs1 = pv[0].y + pv[2].y + pv[4].y + pv[6].y;
            float cs2 = pv[0].z + pv[2].z + pv[4].z + pv[6].z;
            float cs3 = pv[0].w + pv[2].w + pv[4].w + pv[6].w;
            float cs4 = pv[1].x + pv[3].x + pv[5].x + pv[7].x;
            float cs5 = pv[1].y + pv[3].y + pv[5].y + pv[7].y;
            float cs6 = pv[1].z + pv[3].z + pv[5].z + pv[7].z;
            float cs7 = pv[1].w + pv[3].w + pv[5].w + pv[7].w;
            sSb[(pc8 * 8 + 0) * 33 + prow] = cs0;
            sSb[(pc8 * 8 + 1) * 33 + prow] = cs1;
            sSb[(pc8 * 8 + 2) * 33 + prow] = cs2;
            sSb[(pc8 * 8 + 3) * 33 + prow] = cs3;
            sSb[(pc8 * 8 + 4) * 33 + prow] = cs4;
            sSb[(pc8 * 8 + 5) * 33 + prow] = cs5;
            sSb[(pc8 * 8 + 6) * 33 + prow] = cs6;
            sSb[(pc8 * 8 + 7) * 33 + prow] = cs7;
        }
        // convert + store staged tile
#pragma unroll
        for (int q = 0; q < 4; q++) {
            uint4 hq, lq;
            split8(pv[2 * q], pv[2 * q + 1], hq, lq);
            const unsigned o = sw128(prow + q * 32, pc8);
            *(uint4*)(dsm + bufo + o)           = hq;
            *(uint4*)(dsm + bufo + 16384u + o)  = lq;
        }
        __syncthreads();
        // prefetch next chunk (hidden under MMA below)
        if (it + 1 < NIT) {
            const size_t kb = kb0 + (size_t)(it + 1) * 64;
#pragma unroll
            for (int q = 0; q < 4; q++) {
                const float* src = x + (size_t)(b * Cc + prow + q * 32) * Nn + kb + pc8 * 8;
                pv[2 * q]     = *(const float4*)src;
                pv[2 * q + 1] = *(const float4*)(src + 4);
            }
        }
        // finish S reduction for this chunk (threads 0..63, one col each)
        if (tid < 64) {
            float s = 0.f;
#pragma unroll
            for (int i = 0; i < 32; i++) s += sSb[tid * 33 + i];
            g_S[b][kb0 + (size_t)it * 64 + tid] = s;
        }

        const unsigned uH = uBase + bufo, uL = uH + 16384u;
#pragma unroll
        for (int kk = 0; kk < 4; kk++) {
            unsigned aH[2][4], aHf[2][4];
#pragma unroll
            for (int mi = 0; mi < 2; mi++) {
                const unsigned ao = sw128(arow + mi * 16, kk * 2 + asel);
                ldsm4(aH[mi], uH + ao);
#pragma unroll
                for (int j = 0; j < 4; j++) aHf[mi][j] = bhalf(aH[mi][j]);
            }
#pragma unroll
            for (int ni = 0; ni < 4; ni++) {
                unsigned bH[4], bL[4];
                const unsigned bo = sw128(wn * 64 + ni * 16 + brow, kk * 2 + bsel);
                ldsm4(bH, uH + bo);
                ldsm4(bL, uL + bo);
#pragma unroll
                for (int mi = 0; mi < 2; mi++) {
                    mma16816(acc[mi][2 * ni],     aHf[mi], &bH[0]);   // 0.5*H*H^T
                    mma16816(acc[mi][2 * ni],     aH[mi],  &bL[0]);   // H*L^T
                    mma16816(acc[mi][2 * ni + 1], aHf[mi], &bH[2]);
                    mma16816(acc[mi][2 * ni + 1], aH[mi],  &bL[2]);
                }
            }
        }
        // no trailing sync: tiles and sS are double-buffered; the next
        // iteration's sync orders reuse two iterations out.
    }

    float* gp = &g_part[sp][b][0][0];
#pragma unroll
    for (int mi = 0; mi < 2; mi++) {
        const int r0 = wm * 32 + mi * 16 + (lane >> 2);
#pragma unroll
        for (int nb = 0; nb < 8; nb++) {
            const int col = wn * 64 + nb * 8 + (lane & 3) * 2;
            *(float2*)(gp + (size_t)r0 * Cc + col) =
                make_float2(acc[mi][nb][0], acc[mi][nb][1]);
            *(float2*)(gp + (size_t)(r0 + 8) * Cc + col) =
                make_float2(acc[mi][nb][2], acc[mi][nb][3]);
        }
    }
}

// ---------------------------------------------------------------------------
// Kernel 2: G = Psum + Psum^T; row max; bf16 hi/lo split of G.
// One block per batch, 512 threads; smem transpose with stride 132 floats
// (528 B = 16B multiple -> float4 row stores legal; the R14/R15 crash was
//  the 129-stride pad making odd rows 4-mod-16).
// ---------------------------------------------------------------------------
__global__ __launch_bounds__(512)
void k_reduce() {
    extern __shared__ float sP[];   // 128*132 floats
    const int b = blockIdx.x;
    const int t = threadIdx.x;
    const int c = t >> 2;               // row, 4 threads per row
    const int d0 = (t & 3) * 32;        // 32 cols per thread

    __align__(16) float p[32];
#pragma unroll
    for (int j = 0; j < 32; j++) p[j] = 0.f;
#pragma unroll
    for (int sp = 0; sp < SPLITG; sp++) {
#pragma unroll
        for (int j = 0; j < 8; j++) {
            float4 u = *(const float4*)&g_part[sp][b][c][d0 + j * 4];
            p[j * 4 + 0] += u.x; p[j * 4 + 1] += u.y;
            p[j * 4 + 2] += u.z; p[j * 4 + 3] += u.w;
        }
    }
#pragma unroll
    for (int j = 0; j < 8; j++)
        *(float4*)&sP[c * 132 + d0 + j * 4] = *(const float4*)&p[j * 4];
    __syncthreads();

    float G[32];
    float mx = -3.4e38f;
#pragma unroll
    for (int j = 0; j < 32; j++) {
        G[j] = p[j] + sP[(d0 + j) * 132 + c];
        mx = fmaxf(mx, G[j]);
    }
    // combine max across the 4 threads of this row (adjacent lanes)
    mx = fmaxf(mx, __shfl_xor_sync(0xffffffffu, mx, 1));
    mx = fmaxf(mx, __shfl_xor_sync(0xffffffffu, mx, 2));

    // bf16 hi/lo split, vectorized 16B-aligned stores
    __align__(16) __nv_bfloat16 hbuf[32];
    __align__(16) __nv_bfloat16 lbuf[32];
#pragma unroll
    for (int j = 0; j < 32; j++) {
        __nv_bfloat16 h = __float2bfloat16_rn(G[j]);
        hbuf[j] = h;
        lbuf[j] = __float2bfloat16_rn(G[j] - __bfloat162float(h));
    }
#pragma unroll
    for (int j = 0; j < 4; j++) {
        *(uint4*)&g_Gh[b][c][d0 + j * 8] = ((const uint4*)hbuf)[j];
        *(uint4*)&g_Gl[b][c][d0 + j * 8] = ((const uint4*)lbuf)[j];
    }
    if ((t & 3) == 0) g_m[b][c] = mx;
}

// ---------------------------------------------------------------------------
// Kernel 3: att2 = m_c * S[n] - (G*f)[c,n].  A (=G hi/lo) smem-RESIDENT and
// swizzled; B double-buffered; ONE sync per K-chunk.
// ---------------------------------------------------------------------------
__global__ __launch_bounds__(256, 2)
void k_gemm2_mma(const float* __restrict__ x) {
    extern __shared__ __align__(16) char dsm[];
    const int b  = blockIdx.y;
    const int n0 = blockIdx.x * 128;
    const int tid = threadIdx.x;
    const int wid = tid >> 5, lane = tid & 31;
    const int wm = wid & 3, wn = wid >> 2;
    const unsigned uBase = smem_u32(dsm);

    // ---- load resident A = G[b] hi/lo, swizzled 256B rows ----
#pragma unroll
    for (int q = 0; q < 8; q++) {
        const int idx = tid + q * 256;          // 0..2047
        const int row = idx >> 4, col16 = idx & 15;
        const unsigned o = sw256(row, col16);
        *(uint4*)(dsm + o)           = *(const uint4*)&g_Gh[b][row][col16 * 8];
        *(uint4*)(dsm + 32768u + o)  = *(const uint4*)&g_Gl[b][row][col16 * 8];
    }

    float acc[2][8][4];
#pragma unroll
    for (int mi = 0; mi < 2; mi++)
#pragma unroll
        for (int nb = 0; nb < 8; nb++)
#pragma unroll
            for (int q = 0; q < 4; q++) acc[mi][nb][q] = 0.f;

    const int arow = wm * 32 + (lane & 15);
    const int asel = lane >> 4;
    const int btrow = lane & 15;
    const int btcolq = (lane >> 4) * 8;

    const int prow = tid >> 4, pc8 = tid & 15;  // B staging coords
    float4 pB[4];
#pragma unroll
    for (int q = 0; q < 2; q++) {
        const float* src = x + (size_t)(b * Cc + prow + q * 16) * Nn + n0 + pc8 * 8;
        pB[2 * q]     = *(const float4*)src;
        pB[2 * q + 1] = *(const float4*)(src + 4);
    }
    __syncthreads();   // A resident ready

    for (int kt = 0; kt < 4; kt++) {
        const unsigned bOff = 65536u + (unsigned)(kt & 1) * 17408u;
#pragma unroll
        for (int q = 0; q < 2; q++) {
            uint4 hq, lq;
            split8(pB[2 * q], pB[2 * q + 1], hq, lq);
            const unsigned o = (unsigned)((prow + q * 16) * 272 + pc8 * 16);
            *(uint4*)(dsm + bOff + o)          = hq;
            *(uint4*)(dsm + bOff + 8704u + o)  = lq;
        }
        __syncthreads();
        if (kt + 1 < 4) {
            const int k1 = (kt + 1) * 32;
#pragma unroll
            for (int q = 0; q < 2; q++) {
                const float* src =
                    x + (size_t)(b * Cc + k1 + prow + q * 16) * Nn + n0 + pc8 * 8;
                pB[2 * q]     = *(const float4*)src;
                pB[2 * q + 1] = *(const float4*)(src + 4);
            }
        }

        const unsigned uBh = uBase + bOff, uBl = uBh + 8704u;
#pragma unroll
        for (int kk = 0; kk < 2; kk++) {
            unsigned aH[2][4], aL[2][4];
#pragma unroll
            for (int mi = 0; mi < 2; mi++) {
                const unsigned ao = sw256(arow + mi * 16, kt * 4 + kk * 2 + asel);
                ldsm4(aH[mi], uBase + ao);
                ldsm4(aL[mi], uBase + 32768u + ao);
            }
#pragma unroll
            for (int ni = 0; ni < 4; ni++) {
                unsigned bH[4], bL[4];
                const unsigned bo = (unsigned)(
                    (kk * 16 + btrow) * 272 + (wn * 64 + ni * 16 + btcolq) * 2);
                ldsm4t(bH, uBh + bo);
                ldsm4t(bL, uBl + bo);
#pragma unroll
                for (int mi = 0; mi < 2; mi++) {
                    mma16816(acc[mi][2 * ni],     aH[mi], &bH[0]);
                    mma16816(acc[mi][2 * ni],     aH[mi], &bL[0]);
                    mma16816(acc[mi][2 * ni],     aL[mi], &bH[0]);
                    mma16816(acc[mi][2 * ni + 1], aH[mi], &bH[2]);
                    mma16816(acc[mi][2 * ni + 1], aH[mi], &bL[2]);
                    mma16816(acc[mi][2 * ni + 1], aL[mi], &bH[2]);
                }
            }
        }
    }

    // epilogue: att2 = m_c * S[n] - acc
    float* op = g_att2 + (size_t)b * Cc * Nn;
#pragma unroll
    for (int mi = 0; mi < 2; mi++) {
        const int r0 = wm * 32 + mi * 16 + (lane >> 2);
        const float m0 = g_m[b][r0];
        const float m1 = g_m[b][r0 + 8];
#pragma unroll
        for (int nb = 0; nb < 8; nb++) {
            const int col = n0 + wn * 64 + nb * 8 + (lane & 3) * 2;
            const float2 Sv = *(const float2*)&g_S[b][col];
            *(float2*)(op + (size_t)r0 * Nn + col) =
                make_float2(m0 * Sv.x - acc[mi][nb][0],
                            m0 * Sv.y - acc[mi][nb][1]);
            *(float2*)(op + (size_t)(r0 + 8) * Nn + col) =
                make_float2(m1 * Sv.x - acc[mi][nb][2],
                            m1 * Sv.y - acc[mi][nb][3]);
        }
    }
}

// ---------------------------------------------------------------------------
// Kernel 4: depthwise 3x3 conv + bias + softmax(W) + outputs.
// Block = (c, b, quarter): 32 output rows, 34-row halo stage in smem.
// ---------------------------------------------------------------------------
__global__ __launch_bounds__(256)
void k_conv(const float* __restrict__ x, const float* __restrict__ dwW,
            const float* __restrict__ dwB, const float* __restrict__ gamma,
            float* __restrict__ out) {
    __shared__ float sm[34 * 132];
    const int c = blockIdx.x, b = blockIdx.y;
    const int r0 = blockIdx.z * 32;
    const int tid = threadIdx.x;

    for (int i = tid; i < 34 * 132; i += 256) sm[i] = 0.f;
    __syncthreads();

    const float* __restrict__ pl = g_att2 + ((size_t)b * Cc + c) * Nn;
    for (int idx4 = tid; idx4 < 34 * 32; idx4 += 256) {
        const int i = idx4 >> 5, w4 = (idx4 & 31) << 2;
        const int gr = r0 - 1 + i;
        if (gr >= 0 && gr < Hh) {
            float4 u = *(const float4*)(pl + gr * Ww + w4);
            float* rp = sm + i * 132 + 1 + w4;
            rp[0] = u.x; rp[1] = u.y; rp[2] = u.z; rp[3] = u.w;
        }
    }

    float w9[9];
#pragma unroll
    for (int i = 0; i < 9; i++) w9[i] = dwW[c * 9 + i];
    const float bz = dwB[c];
    const float gm = gamma[0];
    __syncthreads();

    const int warp = tid >> 5, lane = tid & 31;
    const float* __restrict__ xp = x + ((size_t)b * Cc + c) * Nn;
    float* __restrict__ op = out + ((size_t)b * Cc + c) * Nn;
    float* __restrict__ ap = out + (size_t)Bb * Cc * Nn + ((size_t)b * Cc + c) * Nn;

    for (int hh = warp; hh < 32; hh += 8) {
        const int h = r0 + hh;
        const int li = hh + 1;
        const int wb = lane << 2;
        float r0v[8], r1v[8], r2v[8];
        {
            float4 a0 = *(const float4*)&sm[(li - 1) * 132 + wb];
            float4 a1 = *(const float4*)&sm[(li - 1) * 132 + wb + 4];
            r0v[0]=a0.x; r0v[1]=a0.y; r0v[2]=a0.z; r0v[3]=a0.w;
            r0v[4]=a1.x; r0v[5]=a1.y; r0v[6]=a1.z; r0v[7]=a1.w;
            float4 b0 = *(const float4*)&sm[(li + 0) * 132 + wb];
            float4 b1 = *(const float4*)&sm[(li + 0) * 132 + wb + 4];
            r1v[0]=b0.x; r1v[1]=b0.y; r1v[2]=b0.z; r1v[3]=b0.w;
            r1v[4]=b1.x; r1v[5]=b1.y; r1v[6]=b1.z; r1v[7]=b1.w;
            float4 c0 = *(const float4*)&sm[(li + 1) * 132 + wb];
            float4 c1 = *(const float4*)&sm[(li + 1) * 132 + wb + 4];
            r2v[0]=c0.x; r2v[1]=c0.y; r2v[2]=c0.z; r2v[3]=c0.w;
            r2v[4]=c1.x; r2v[5]=c1.y; r2v[6]=c1.z; r2v[7]=c1.w;
        }
        float v[4];
#pragma unroll
        for (int j = 0; j < 4; j++) {
            float s = bz;
            s = fmaf(r0v[j],     w9[0], s);
            s = fmaf(r0v[j + 1], w9[1], s);
            s = fmaf(r0v[j + 2], w9[2], s);
            s = fmaf(r1v[j],     w9[3], s);
            s = fmaf(r1v[j + 1], w9[4], s);
            s = fmaf(r1v[j + 2], w9[5], s);
            s = fmaf(r2v[j],     w9[6], s);
            s = fmaf(r2v[j + 1], w9[7], s);
            s = fmaf(r2v[j + 2], w9[8], s);
            v[j] = s;
        }
        float mx = fmaxf(fmaxf(v[0], v[1]), fmaxf(v[2], v[3]));
#pragma unroll
        for (int o = 16; o; o >>= 1) mx = fmaxf(mx, __shfl_xor_sync(0xffffffffu, mx, o));
        float e[4]; float ssum = 0.f;
#pragma unroll
        for (int j = 0; j < 4; j++) { e[j] = __expf(v[j] - mx); ssum += e[j]; }
#pragma unroll
        for (int o = 16; o; o >>= 1) ssum += __shfl_xor_sync(0xffffffffu, ssum, o);
        const float inv = 1.0f / ssum;

        float4 xv = *(const float4*)(xp + h * Ww + wb);
        float4 av = make_float4(e[0] * inv, e[1] * inv, e[2] * inv, e[3] * inv);
        *(float4*)(ap + h * Ww + wb) = av;
        *(float4*)(op + h * Ww + wb) = make_float4(
            fmaf(gm, av.x, xv.x), fmaf(gm, av.y, xv.y),
            fmaf(gm, av.z, xv.z), fmaf(gm, av.w, xv.w));
    }
}

// ---------------------------------------------------------------------------
extern "C" void kernel_launch(void* const* d_in, const int* in_sizes, int n_in,
                              void* d_out, int out_size) {
    (void)in_sizes; (void)n_in; (void)out_size;
    const float* x    = (const float*)d_in[0];
    const float* dwW  = (const float*)d_in[1];
    const float* dwB  = (const float*)d_in[2];
    const float* gm   = (const float*)d_in[3];
    float* out = (float*)d_out;

    cudaFuncSetAttribute(k_gram_mma,
                         cudaFuncAttributeMaxDynamicSharedMemorySize, 82432);
    cudaFuncSetAttribute(k_reduce,
                         cudaFuncAttributeMaxDynamicSharedMemorySize, 128 * 132 * 4);
    cudaFuncSetAttribute(k_gemm2_mma,
                         cudaFuncAttributeMaxDynamicSharedMemorySize, 100352);

    k_gram_mma <<<dim3(SPLITG, Bb), 256, 82432>>>(x);
    k_reduce   <<<Bb, 512, 128 * 132 * 4>>>();
    k_gemm2_mma<<<dim3(Nn / 128, Bb), 256, 100352>>>(x);
    k_conv     <<<dim3(Cc, Bb, 4), 256>>>(x, dwW, dwB, gm, out);
}